// round 1
// baseline (speedup 1.0000x reference)
#include <cuda_runtime.h>
#include <cuda_bf16.h>
#include <math.h>

// Problem constants
#define NN 50000
#define EE 800000
#define ETOT (EE + NN)   // 850000 (edges + self loops)
#define FF 128
#define HH4 4
#define DD 64
#define GG 32
#define CC 3

// ---------------- device scratch (static; no allocation allowed) ----------------
__device__ float g_bufA[(size_t)NN * 256];
__device__ float g_bufB[(size_t)NN * 256];
__device__ float g_als[NN * 4];
__device__ float g_ald[NN * 4];
__device__ int   g_rowptr[NN + 1];
__device__ int   g_cursor[NN];         // counts, then running cursor
__device__ int   g_esrc[ETOT];
__device__ int   g_eid[ETOT];
__device__ float g_pool[GG * DD];
__device__ float g_cnt[GG];
__device__ int   g_is64_ei;
__device__ int   g_is64_b;

// ---------------- helpers ----------------
__device__ __forceinline__ float lrelu(float x) { return x > 0.f ? x : 0.2f * x; }

// read index i from an index buffer that is either int32 or int64 (low word)
__device__ __forceinline__ int ld_idx(const void* p, long long i, int is64) {
    if (is64) return ((const int*)p)[2 * i];   // little-endian low word
    return ((const int*)p)[i];
}

// ---------------- dtype detection ----------------
__global__ void detect_k(const void* ei, const void* batch) {
    const int* p = (const int*)ei;
    bool z = true;
    #pragma unroll
    for (int i = 0; i < 16; i++) z = z && (p[2 * i + 1] == 0);
    g_is64_ei = z ? 1 : 0;
    // batch is sorted ascending, last values ~G-1 != 0 for int32.
    const int* q = (const int*)batch;
    bool zb = true;
    #pragma unroll
    for (int i = 0; i < 16; i++) zb = zb && (q[NN - 1 - 2 * i] == 0);
    g_is64_b = zb ? 1 : 0;
}

// ---------------- zero scratch ----------------
__global__ void zero_k() {
    int i = blockIdx.x * blockDim.x + threadIdx.x;
    if (i < NN) g_cursor[i] = 0;
    if (i < GG * DD) g_pool[i] = 0.f;
    if (i < GG) g_cnt[i] = 0.f;
}

// ---------------- CSR build ----------------
__global__ void count_k(const void* ei) {
    long long e = (long long)blockIdx.x * blockDim.x + threadIdx.x;
    if (e >= ETOT) return;
    int is64 = g_is64_ei;
    int d = (e < EE) ? ld_idx(ei, (long long)EE + e, is64) : (int)(e - EE);
    atomicAdd(&g_cursor[d], 1);
}

__global__ void scan_k() {
    __shared__ int sh[1024];
    __shared__ int carry;
    int t = threadIdx.x;
    if (t == 0) carry = 0;
    __syncthreads();
    for (int base = 0; base < NN; base += 1024) {
        int idx = base + t;
        int v = (idx < NN) ? g_cursor[idx] : 0;
        sh[t] = v;
        __syncthreads();
        #pragma unroll
        for (int off = 1; off < 1024; off <<= 1) {
            int tv = (t >= off) ? sh[t - off] : 0;
            __syncthreads();
            sh[t] += tv;
            __syncthreads();
        }
        int excl = carry + sh[t] - v;
        if (idx < NN) { g_rowptr[idx] = excl; g_cursor[idx] = excl; }
        __syncthreads();
        if (t == 1023) carry += sh[1023];
        __syncthreads();
    }
    if (t == 0) g_rowptr[NN] = carry;
}

__global__ void scatter_k(const void* ei) {
    long long e = (long long)blockIdx.x * blockDim.x + threadIdx.x;
    if (e >= ETOT) return;
    int is64 = g_is64_ei;
    int s, d;
    if (e < EE) {
        s = ld_idx(ei, e, is64);
        d = ld_idx(ei, (long long)EE + e, is64);
    } else {
        s = d = (int)(e - EE);
    }
    int pos = atomicAdd(&g_cursor[d], 1);
    g_esrc[pos] = s;
    g_eid[pos]  = (int)e;
}

// ---------------- tiled SGEMM: C[M,Nc] = A[M,K] @ B[K,Nc] ----------------
// BM=BN=64, BK=16, 256 threads, 4x4 outputs/thread. K%16==0, Nc%64==0 assumed.
__global__ void __launch_bounds__(256) sgemm_k(const float* __restrict__ A,
                                               const float* __restrict__ B,
                                               float* __restrict__ Cm,
                                               int M, int K, int Nc) {
    __shared__ float As[16][68];
    __shared__ float Bs[16][64];
    int tid = threadIdx.x;
    int tx = tid & 15, ty = tid >> 4;
    int rowBase = blockIdx.y * 64;
    int colBase = blockIdx.x * 64;
    float acc[4][4] = {};

    int ar = tid >> 2;          // 0..63
    int ak = (tid & 3) << 2;    // 0,4,8,12
    int br = tid >> 4;          // 0..15
    int bc = (tid & 15) << 2;   // 0..60

    for (int kt = 0; kt < K; kt += 16) {
        float4 av = make_float4(0.f, 0.f, 0.f, 0.f);
        if (rowBase + ar < M)
            av = *(const float4*)(A + (size_t)(rowBase + ar) * K + kt + ak);
        As[ak + 0][ar] = av.x; As[ak + 1][ar] = av.y;
        As[ak + 2][ar] = av.z; As[ak + 3][ar] = av.w;
        float4 bv = *(const float4*)(B + (size_t)(kt + br) * Nc + colBase + bc);
        *(float4*)&Bs[br][bc] = bv;
        __syncthreads();
        #pragma unroll
        for (int k = 0; k < 16; k++) {
            float a0 = As[k][ty * 4 + 0], a1 = As[k][ty * 4 + 1];
            float a2 = As[k][ty * 4 + 2], a3 = As[k][ty * 4 + 3];
            float4 b4 = *(float4*)&Bs[k][tx * 4];
            acc[0][0] += a0 * b4.x; acc[0][1] += a0 * b4.y; acc[0][2] += a0 * b4.z; acc[0][3] += a0 * b4.w;
            acc[1][0] += a1 * b4.x; acc[1][1] += a1 * b4.y; acc[1][2] += a1 * b4.z; acc[1][3] += a1 * b4.w;
            acc[2][0] += a2 * b4.x; acc[2][1] += a2 * b4.y; acc[2][2] += a2 * b4.z; acc[2][3] += a2 * b4.w;
            acc[3][0] += a3 * b4.x; acc[3][1] += a3 * b4.y; acc[3][2] += a3 * b4.z; acc[3][3] += a3 * b4.w;
        }
        __syncthreads();
    }
    #pragma unroll
    for (int i = 0; i < 4; i++) {
        int row = rowBase + ty * 4 + i;
        if (row < M) {
            float4 v = make_float4(acc[i][0], acc[i][1], acc[i][2], acc[i][3]);
            *(float4*)(Cm + (size_t)row * Nc + colBase + tx * 4) = v;
        }
    }
}

// ---------------- per-node attention logits al_s, al_d ----------------
template <int HEADS>
__global__ void __launch_bounds__(256) compute_al_k(const float* __restrict__ h,
                                                    const float* __restrict__ a_s,
                                                    const float* __restrict__ a_d) {
    constexpr int HD = HEADS * DD;
    constexpr int LPH = 32 / HEADS;       // lanes per head
    constexpr int CPL = DD / LPH;         // cols per lane
    int wid = (blockIdx.x * blockDim.x + threadIdx.x) >> 5;
    int lane = threadIdx.x & 31;
    if (wid >= NN) return;
    int hh = lane / LPH;
    int j = lane % LPH;
    const float* row = h + (size_t)wid * HD + hh * DD + j * CPL;
    const float* asr = a_s + hh * DD + j * CPL;
    const float* adr = a_d + hh * DD + j * CPL;
    float ss = 0.f, sd = 0.f;
    #pragma unroll
    for (int c = 0; c < CPL; c++) {
        float v = row[c];
        ss += v * asr[c];
        sd += v * adr[c];
    }
    #pragma unroll
    for (int off = LPH / 2; off; off >>= 1) {
        ss += __shfl_down_sync(0xffffffffu, ss, off);
        sd += __shfl_down_sync(0xffffffffu, sd, off);
    }
    if (j == 0) {
        g_als[wid * HEADS + hh] = ss;
        g_ald[wid * HEADS + hh] = sd;
    }
}

// ---------------- GAT aggregation (warp per dst) ----------------
template <int HEADS, bool DOELU>
__global__ void __launch_bounds__(256) aggregate_k(const float* __restrict__ hlin,
                                                   const float* __restrict__ bias,
                                                   float* __restrict__ hout,
                                                   float* __restrict__ att) {
    constexpr int HD = HEADS * DD;
    int wid = (blockIdx.x * blockDim.x + threadIdx.x) >> 5;
    int lane = threadIdx.x & 31;
    if (wid >= NN) return;
    int n = wid;
    int st = g_rowptr[n], en = g_rowptr[n + 1];

    float ald[HEADS];
    if (HEADS == 4) {
        float4 v = ((const float4*)g_ald)[n];
        ald[0] = v.x; ald[1] = v.y; ald[2] = v.z; ald[3] = v.w;
    } else {
        ald[0] = g_ald[n];
    }

    float m[HEADS];
    #pragma unroll
    for (int h = 0; h < HEADS; h++) m[h] = -1e30f;

    // pass 1: segment max (lanes parallel over edges)
    for (int i = st + lane; i < en; i += 32) {
        int s = g_esrc[i];
        if (HEADS == 4) {
            float4 av = ((const float4*)g_als)[s];
            m[0] = fmaxf(m[0], lrelu(av.x + ald[0]));
            m[1] = fmaxf(m[1], lrelu(av.y + ald[1]));
            m[2] = fmaxf(m[2], lrelu(av.z + ald[2]));
            m[3] = fmaxf(m[3], lrelu(av.w + ald[3]));
        } else {
            m[0] = fmaxf(m[0], lrelu(g_als[s] + ald[0]));
        }
    }
    #pragma unroll
    for (int h = 0; h < HEADS; h++)
        #pragma unroll
        for (int off = 16; off; off >>= 1)
            m[h] = fmaxf(m[h], __shfl_xor_sync(0xffffffffu, m[h], off));

    float ssum[HEADS];
    #pragma unroll
    for (int h = 0; h < HEADS; h++) ssum[h] = 0.f;

    // pass 2: exp sums + weighted accumulation (lanes parallel over feature dim)
    if (HEADS == 4) {
        bool lo = lane < 16;
        float4 a0 = make_float4(0.f, 0.f, 0.f, 0.f), a1 = a0;
        for (int i = st; i < en; i++) {
            int s = g_esrc[i];
            float4 av = ((const float4*)g_als)[s];
            float ex0 = __expf(lrelu(av.x + ald[0]) - m[0]);
            float ex1 = __expf(lrelu(av.y + ald[1]) - m[1]);
            float ex2 = __expf(lrelu(av.z + ald[2]) - m[2]);
            float ex3 = __expf(lrelu(av.w + ald[3]) - m[3]);
            ssum[0] += ex0; ssum[1] += ex1; ssum[2] += ex2; ssum[3] += ex3;
            const float4* h4 = (const float4*)(hlin + (size_t)s * 256);
            float4 v0 = h4[lane], v1 = h4[32 + lane];
            float e01 = lo ? ex0 : ex1;
            float e23 = lo ? ex2 : ex3;
            a0.x += e01 * v0.x; a0.y += e01 * v0.y; a0.z += e01 * v0.z; a0.w += e01 * v0.w;
            a1.x += e23 * v1.x; a1.y += e23 * v1.y; a1.z += e23 * v1.z; a1.w += e23 * v1.w;
        }
        float s01 = lo ? ssum[0] : ssum[1];
        float s23 = lo ? ssum[2] : ssum[3];
        const float4* b4 = (const float4*)bias;
        float4 bb0 = b4[lane], bb1 = b4[32 + lane];
        float4 o0, o1;
        o0.x = a0.x / s01 + bb0.x; o0.y = a0.y / s01 + bb0.y;
        o0.z = a0.z / s01 + bb0.z; o0.w = a0.w / s01 + bb0.w;
        o1.x = a1.x / s23 + bb1.x; o1.y = a1.y / s23 + bb1.y;
        o1.z = a1.z / s23 + bb1.z; o1.w = a1.w / s23 + bb1.w;
        if (DOELU) {
            o0.x = o0.x > 0.f ? o0.x : __expf(o0.x) - 1.f;
            o0.y = o0.y > 0.f ? o0.y : __expf(o0.y) - 1.f;
            o0.z = o0.z > 0.f ? o0.z : __expf(o0.z) - 1.f;
            o0.w = o0.w > 0.f ? o0.w : __expf(o0.w) - 1.f;
            o1.x = o1.x > 0.f ? o1.x : __expf(o1.x) - 1.f;
            o1.y = o1.y > 0.f ? o1.y : __expf(o1.y) - 1.f;
            o1.z = o1.z > 0.f ? o1.z : __expf(o1.z) - 1.f;
            o1.w = o1.w > 0.f ? o1.w : __expf(o1.w) - 1.f;
        }
        float4* ho = (float4*)(hout + (size_t)n * 256);
        ho[lane] = o0;
        ho[32 + lane] = o1;
    } else {
        float2 a = make_float2(0.f, 0.f);
        for (int i = st; i < en; i++) {
            int s = g_esrc[i];
            float ex = __expf(lrelu(g_als[s] + ald[0]) - m[0]);
            ssum[0] += ex;
            const float2* h2 = (const float2*)(hlin + (size_t)s * 64);
            float2 v = h2[lane];
            a.x += ex * v.x;
            a.y += ex * v.y;
        }
        const float2* b2 = (const float2*)bias;
        float2 bb = b2[lane];
        float2 o;
        o.x = a.x / ssum[0] + bb.x;
        o.y = a.y / ssum[0] + bb.y;
        if (DOELU) {
            o.x = o.x > 0.f ? o.x : __expf(o.x) - 1.f;
            o.y = o.y > 0.f ? o.y : __expf(o.y) - 1.f;
        }
        ((float2*)(hout + (size_t)n * 64))[lane] = o;
    }

    // pass 3: write alpha in original edge order
    for (int i = st + lane; i < en; i += 32) {
        int s = g_esrc[i];
        long long id = g_eid[i];
        if (HEADS == 4) {
            float4 av = ((const float4*)g_als)[s];
            att[id * 4 + 0] = __expf(lrelu(av.x + ald[0]) - m[0]) / ssum[0];
            att[id * 4 + 1] = __expf(lrelu(av.y + ald[1]) - m[1]) / ssum[1];
            att[id * 4 + 2] = __expf(lrelu(av.z + ald[2]) - m[2]) / ssum[2];
            att[id * 4 + 3] = __expf(lrelu(av.w + ald[3]) - m[3]) / ssum[3];
        } else {
            att[id] = __expf(lrelu(g_als[s] + ald[0]) - m[0]) / ssum[0];
        }
    }
}

// ---------------- global mean pool (sum + count) ----------------
__global__ void pool_k(const void* batch, const float* __restrict__ h3) {
    long long t = (long long)blockIdx.x * blockDim.x + threadIdx.x;
    if (t >= (long long)NN * DD) return;
    int n = (int)(t >> 6);
    int d = (int)(t & 63);
    int g = ld_idx(batch, n, g_is64_b);
    atomicAdd(&g_pool[g * DD + d], h3[t]);
    if (d == 0) atomicAdd(&g_cnt[g], 1.f);
}

// ---------------- classifier ----------------
__global__ void classifier_k(const float* __restrict__ Wc1, const float* __restrict__ bc1,
                             const float* __restrict__ Wc2, const float* __restrict__ bc2,
                             float* __restrict__ out) {
    __shared__ float hid[GG][33];
    int t = threadIdx.x;
    for (int idx = t; idx < GG * 32; idx += blockDim.x) {
        int g = idx >> 5, j = idx & 31;
        float inv = 1.f / fmaxf(g_cnt[g], 1.f);
        float s = bc1[j];
        #pragma unroll
        for (int d = 0; d < DD; d++)
            s += (g_pool[g * DD + d] * inv) * Wc1[d * 32 + j];
        hid[g][j] = fmaxf(s, 0.f);
    }
    __syncthreads();
    for (int idx = t; idx < GG * CC; idx += blockDim.x) {
        int g = idx / CC, c = idx % CC;
        float s = bc2[c];
        #pragma unroll
        for (int j = 0; j < 32; j++)
            s += hid[g][j] * Wc2[j * CC + c];
        out[g * CC + c] = s;
    }
}

// ---------------- launch ----------------
extern "C" void kernel_launch(void* const* d_in, const int* in_sizes, int n_in,
                              void* d_out, int out_size) {
    const float* x   = (const float*)d_in[0];
    const void*  ei  = d_in[1];
    const void*  bat = d_in[2];
    const float* W1  = (const float*)d_in[3];
    const float* as1 = (const float*)d_in[4];
    const float* ad1 = (const float*)d_in[5];
    const float* b1  = (const float*)d_in[6];
    const float* W2  = (const float*)d_in[7];
    const float* as2 = (const float*)d_in[8];
    const float* ad2 = (const float*)d_in[9];
    const float* b2  = (const float*)d_in[10];
    const float* W3  = (const float*)d_in[11];
    const float* as3 = (const float*)d_in[12];
    const float* ad3 = (const float*)d_in[13];
    const float* b3  = (const float*)d_in[14];
    const float* Wc1 = (const float*)d_in[15];
    const float* bc1 = (const float*)d_in[16];
    const float* Wc2 = (const float*)d_in[17];
    const float* bc2 = (const float*)d_in[18];

    float* out  = (float*)d_out;
    float* att1 = out + GG * CC;
    float* att2 = att1 + (size_t)ETOT * 4;
    float* att3 = att2 + (size_t)ETOT * 4;

    float *bufA, *bufB;
    cudaGetSymbolAddress((void**)&bufA, g_bufA);
    cudaGetSymbolAddress((void**)&bufB, g_bufB);

    const int NB_E = (ETOT + 255) / 256;
    const int NB_N = (NN + 255) / 256;
    const int NB_W = (NN * 32 + 255) / 256;   // one warp per node

    detect_k<<<1, 1>>>(ei, bat);
    zero_k<<<NB_N, 256>>>();
    count_k<<<NB_E, 256>>>(ei);
    scan_k<<<1, 1024>>>();
    scatter_k<<<NB_E, 256>>>(ei);

    // Layer 1: h = x @ W1 -> [N, 256]
    sgemm_k<<<dim3(256 / 64, (NN + 63) / 64), 256>>>(x, W1, bufA, NN, FF, 256);
    compute_al_k<4><<<NB_W, 256>>>(bufA, as1, ad1);
    aggregate_k<4, true><<<NB_W, 256>>>(bufA, b1, bufB, att1);

    // Layer 2
    sgemm_k<<<dim3(256 / 64, (NN + 63) / 64), 256>>>(bufB, W2, bufA, NN, 256, 256);
    compute_al_k<4><<<NB_W, 256>>>(bufA, as2, ad2);
    aggregate_k<4, true><<<NB_W, 256>>>(bufA, b2, bufB, att2);

    // Layer 3: heads=1, D=64, no ELU, no concat (mean over 1 head = identity)
    sgemm_k<<<dim3(64 / 64, (NN + 63) / 64), 256>>>(bufB, W3, bufA, NN, 256, 64);
    compute_al_k<1><<<NB_W, 256>>>(bufA, as3, ad3);
    aggregate_k<1, false><<<NB_W, 256>>>(bufA, b3, bufB, att3);

    // Pool + classify
    pool_k<<<(int)(((long long)NN * DD + 255) / 256), 256>>>(bat, bufB);
    classifier_k<<<1, 256>>>(Wc1, bc1, Wc2, bc2, out);
}